// round 16
// baseline (speedup 1.0000x reference)
#include <cuda_runtime.h>
#include <cuda_fp16.h>

#define N_NODES 50000
#define HF 128          // H*F
#define H_HEADS 4
#define DEG_CAP 128     // bucket capacity; deg ~ Poisson(16), P(>128) < 1e-60
#define GBLK 128        // nodes per GEMM block
#define KCH 32          // K chunk (2 k-steps of 16)
#define XS_STRIDE 40    // fp16 per row (80B: conflict-free ldmatrix, 16B-aligned)
#define WS_STRIDE 136   // fp16 per row (272B: conflict-free ldmatrix.trans)

// ---------------- scratch (static device globals; no allocation) ----------------
__device__ float  g_z[N_NODES * HF];
__device__ float  g_acc1[N_NODES * HF];  // layer-1 base -> elu(h1)
__device__ float  g_acc2[N_NODES * HF];  // layer-2 base (residual + bias)
__device__ float  g_el[N_NODES * H_HEADS];
__device__ float  g_er[N_NODES * H_HEADS];
__device__ __half g_xh[N_NODES * HF];    // fp16 GEMM input
__device__ __half g_w1h[HF * HF];
__device__ __half g_w2h[HF * HF];
__device__ int    g_cnt[N_NODES];
__device__ int    g_bucket[N_NODES * DEG_CAP];    // 25.6 MB: src per slot
__device__ int    g_posarr[1000000];              // edge -> bucket slot
__device__ float4 g_evb[N_NODES * DEG_CAP];       // 102 MB: exp terms per slot (sparse-touched)

__device__ __forceinline__ float leaky(float v) { return v > 0.f ? v : 0.2f * v; }
__device__ __forceinline__ float elu(float v)   { return v > 0.f ? v : (__expf(v) - 1.f); }

__device__ __forceinline__ unsigned smem_u32(const void* p) {
    unsigned a;
    asm("{ .reg .u64 t; cvta.to.shared.u64 t, %1; cvt.u32.u64 %0, t; }" : "=r"(a) : "l"(p));
    return a;
}

// ---------------- bucket fill (+ slot record) ----------------
__global__ void fill_bucket_kernel(const int* __restrict__ src, const int* __restrict__ dst,
                                   int E, int* __restrict__ cnt, int* __restrict__ bucket,
                                   int* __restrict__ posarr) {
    int i = blockIdx.x * blockDim.x + threadIdx.x;
    int e0 = i * 4;
    if (e0 + 4 <= E) {
        int4 d4 = *reinterpret_cast<const int4*>(dst + e0);
        int4 s4 = *reinterpret_cast<const int4*>(src + e0);
        int sl0 = d4.x * DEG_CAP + atomicAdd(&cnt[d4.x], 1);
        int sl1 = d4.y * DEG_CAP + atomicAdd(&cnt[d4.y], 1);
        int sl2 = d4.z * DEG_CAP + atomicAdd(&cnt[d4.z], 1);
        int sl3 = d4.w * DEG_CAP + atomicAdd(&cnt[d4.w], 1);
        bucket[sl0] = s4.x;
        bucket[sl1] = s4.y;
        bucket[sl2] = s4.z;
        bucket[sl3] = s4.w;
        *reinterpret_cast<int4*>(posarr + e0) = make_int4(sl0, sl1, sl2, sl3);
    } else {
        for (int e = e0; e < E; e++) {
            int dn = dst[e];
            int slot = dn * DEG_CAP + atomicAdd(&cnt[dn], 1);
            bucket[slot] = src[e];
            posarr[e] = slot;
        }
    }
}

// ---------------- converters ----------------
__global__ void conv_x_kernel(const float* __restrict__ x, const float* __restrict__ bias,
                              __half* __restrict__ xh, float* __restrict__ base) {
    int idx = blockIdx.x * blockDim.x + threadIdx.x;       // float4 index
    if (idx >= N_NODES * HF / 4) return;
    float4 v = reinterpret_cast<const float4*>(x)[idx];
    int c = (idx * 4) & (HF - 1);
    float4 b = *reinterpret_cast<const float4*>(&bias[c]);
    reinterpret_cast<float4*>(base)[idx] =
        make_float4(v.x + b.x, v.y + b.y, v.z + b.z, v.w + b.w);
    __half2 h0 = __floats2half2_rn(v.x, v.y);
    __half2 h1 = __floats2half2_rn(v.z, v.w);
    uint2 u = make_uint2(*reinterpret_cast<unsigned*>(&h0), *reinterpret_cast<unsigned*>(&h1));
    reinterpret_cast<uint2*>(xh)[idx] = u;
}

__global__ void conv_w_kernel(const float* __restrict__ W1, const float* __restrict__ W2,
                              __half* __restrict__ W1h, __half* __restrict__ W2h) {
    int i = blockIdx.x * blockDim.x + threadIdx.x;
    if (i < HF * HF) {
        W1h[i] = __float2half_rn(W1[i]);
        W2h[i] = __float2half_rn(W2[i]);
    }
}

// ---------------- K1: tensor-core GEMM (mma.sync m16n8k16 f16->f32) --------------------
__global__ __launch_bounds__(256)
void gemm_attn_kernel(const __half* __restrict__ xh,
                      const __half* __restrict__ Wh,
                      const float* __restrict__ al,
                      const float* __restrict__ ar,
                      float* __restrict__ z,
                      float* __restrict__ el,
                      float* __restrict__ er)
{
    __shared__ __half xs[GBLK][XS_STRIDE];   // 10.2 KB
    __shared__ __half ws[KCH][WS_STRIDE];    //  8.7 KB

    const int tid  = threadIdx.x;
    const int w    = tid >> 5;
    const int lane = tid & 31;
    const int n0   = blockIdx.x * GBLK;

    float acc[16][4];
    #pragma unroll
    for (int nt = 0; nt < 16; nt++)
        #pragma unroll
        for (int c = 0; c < 4; c++) acc[nt][c] = 0.f;

    const int amat = lane >> 3;
    const int arow = (w << 4) + (lane & 7) + ((amat & 1) << 3);
    const int acol = (amat >> 1) << 3;
    const unsigned a_addr0 = smem_u32(&xs[arow][acol]);

    const int bl    = lane & 15;
    const int bkrow = (bl & 7) + ((bl >> 3) << 3);
    const unsigned b_addr0 = smem_u32(&ws[0][0]) + (unsigned)bkrow * (WS_STRIDE * 2);

    for (int kc = 0; kc < HF; kc += KCH) {
        #pragma unroll
        for (int it = 0; it < 2; it++) {
            int i   = tid + it * 256;
            int row = i >> 2, seg = i & 3;
            int n   = n0 + row;
            uint4 v = make_uint4(0u, 0u, 0u, 0u);
            if (n < N_NODES)
                v = *reinterpret_cast<const uint4*>(&xh[n * HF + kc + seg * 8]);
            *reinterpret_cast<uint4*>(&xs[row][seg * 8]) = v;
        }
        #pragma unroll
        for (int it = 0; it < 2; it++) {
            int i  = tid + it * 256;
            int k  = i >> 4, c8 = i & 15;
            uint4 v = *reinterpret_cast<const uint4*>(&Wh[(kc + k) * HF + c8 * 8]);
            *reinterpret_cast<uint4*>(&ws[k][c8 * 8]) = v;
        }
        __syncthreads();

        #pragma unroll
        for (int s = 0; s < 2; s++) {
            unsigned a0, a1, a2, a3;
            asm volatile("ldmatrix.sync.aligned.m8n8.x4.shared.b16 {%0,%1,%2,%3}, [%4];"
                         : "=r"(a0), "=r"(a1), "=r"(a2), "=r"(a3)
                         : "r"(a_addr0 + (unsigned)(s * 16 * 2)));
            unsigned b_base = b_addr0 + (unsigned)(s * 16 * (WS_STRIDE * 2));
            #pragma unroll
            for (int nt = 0; nt < 16; nt++) {
                unsigned b0, b1;
                asm volatile("ldmatrix.sync.aligned.m8n8.x2.trans.shared.b16 {%0,%1}, [%2];"
                             : "=r"(b0), "=r"(b1)
                             : "r"(b_base + (unsigned)(nt * 16)));
                asm volatile("mma.sync.aligned.m16n8k16.row.col.f32.f16.f16.f32 "
                             "{%0,%1,%2,%3},{%4,%5,%6,%7},{%8,%9},{%0,%1,%2,%3};"
                             : "+f"(acc[nt][0]), "+f"(acc[nt][1]),
                               "+f"(acc[nt][2]), "+f"(acc[nt][3])
                             : "r"(a0), "r"(a1), "r"(a2), "r"(a3), "r"(b0), "r"(b1));
            }
        }
        __syncthreads();
    }

    const int g = lane >> 2, t = lane & 3;
    const int nr0 = n0 + (w << 4) + g;
    const int nr1 = nr0 + 8;
    const bool v0 = (nr0 < N_NODES), v1 = (nr1 < N_NODES);

    float pl0[H_HEADS], pr0[H_HEADS], pl1[H_HEADS], pr1[H_HEADS];
    #pragma unroll
    for (int h = 0; h < H_HEADS; h++) { pl0[h] = pr0[h] = pl1[h] = pr1[h] = 0.f; }

    #pragma unroll
    for (int nt = 0; nt < 16; nt++) {
        int c = nt * 8 + t * 2;
        if (v0) *reinterpret_cast<float2*>(&z[nr0 * HF + c]) = make_float2(acc[nt][0], acc[nt][1]);
        if (v1) *reinterpret_cast<float2*>(&z[nr1 * HF + c]) = make_float2(acc[nt][2], acc[nt][3]);
        float2 alv = *reinterpret_cast<const float2*>(&al[c]);
        float2 arv = *reinterpret_cast<const float2*>(&ar[c]);
        int h = nt >> 2;
        pl0[h] += acc[nt][0] * alv.x + acc[nt][1] * alv.y;
        pr0[h] += acc[nt][0] * arv.x + acc[nt][1] * arv.y;
        pl1[h] += acc[nt][2] * alv.x + acc[nt][3] * alv.y;
        pr1[h] += acc[nt][2] * arv.x + acc[nt][3] * arv.y;
    }
    #pragma unroll
    for (int h = 0; h < H_HEADS; h++) {
        float a = pl0[h], b = pr0[h], cc = pl1[h], dd = pr1[h];
        a += __shfl_down_sync(0xffffffffu, a, 2);  a += __shfl_down_sync(0xffffffffu, a, 1);
        b += __shfl_down_sync(0xffffffffu, b, 2);  b += __shfl_down_sync(0xffffffffu, b, 1);
        cc += __shfl_down_sync(0xffffffffu, cc, 2); cc += __shfl_down_sync(0xffffffffu, cc, 1);
        dd += __shfl_down_sync(0xffffffffu, dd, 2); dd += __shfl_down_sync(0xffffffffu, dd, 1);
        if (t == 0) {
            if (v0) { el[nr0 * H_HEADS + h] = a;  er[nr0 * H_HEADS + h] = b;  }
            if (v1) { el[nr1 * H_HEADS + h] = cc; er[nr1 * H_HEADS + h] = dd; }
        }
    }
}

// ---------------- edge-parallel attention: ev -> bucket-slot order ----------------------
__global__ void attn_edge_kernel(const int* __restrict__ src, const int* __restrict__ dst,
                                 const int* __restrict__ posarr, int E,
                                 const float* __restrict__ el, const float* __restrict__ er,
                                 float4* __restrict__ evb) {
    int e = blockIdx.x * blockDim.x + threadIdx.x;
    if (e >= E) return;
    int sn = src[e], dn = dst[e];
    float4 el4 = *reinterpret_cast<const float4*>(el + sn * H_HEADS);
    float4 er4 = *reinterpret_cast<const float4*>(er + dn * H_HEADS);
    float4 ev;
    ev.x = __expf(leaky(el4.x + er4.x));
    ev.y = __expf(leaky(el4.y + er4.y));
    ev.z = __expf(leaky(el4.z + er4.z));
    ev.w = __expf(leaky(el4.w + er4.w));
    evb[posarr[e]] = ev;
}

// ---------------- aggregate: sequential bucket+ev streams, z-gather only on chain -------
// MODE 0: elu(result) -> hio ; fp16 copy -> xh ; result+b2 -> base2
// MODE 1: head-mean + projection -> out[n]
template <int MODE>
__global__ __launch_bounds__(256)
void gat_aggregate_kernel(const int* __restrict__ cnt,
                          const int* __restrict__ bucket,
                          const float* __restrict__ evf,   // g_evb as float*
                          const float* __restrict__ z,
                          float* __restrict__ hio,
                          __half* __restrict__ xh, float* __restrict__ base2,
                          const float* __restrict__ b2,
                          const float* __restrict__ Wp, const float* __restrict__ bp,
                          float* __restrict__ out)
{
    const int wid  = threadIdx.x >> 5;
    const int lane = threadIdx.x & 31;
    const int n    = blockIdx.x * 8 + wid;
    if (n >= N_NODES) return;

    const int beg = n * DEG_CAP;
    const int d   = cnt[n];
    const int h   = lane >> 3;

    float  s   = 0.f;
    float4 acc = make_float4(0.f, 0.f, 0.f, 0.f);

    for (int i = 0; i < d; ++i) {
        int   sn = __ldg(&bucket[beg + i]);                    // sequential, prefetchable
        float ev = __ldg(&evf[(beg + i) * 4 + h]);             // sequential, prefetchable
        float4 zv = *reinterpret_cast<const float4*>(z + sn * HF + lane * 4);
        s     += ev;
        acc.x += ev * zv.x;
        acc.y += ev * zv.y;
        acc.z += ev * zv.z;
        acc.w += ev * zv.w;
    }

    const float sinv = 1.f / fmaxf(s, 1e-9f);
    float4 base = *reinterpret_cast<const float4*>(hio + n * HF + lane * 4);
    acc.x = base.x + acc.x * sinv;
    acc.y = base.y + acc.y * sinv;
    acc.z = base.z + acc.z * sinv;
    acc.w = base.w + acc.w * sinv;

    if (MODE == 0) {
        acc.x = elu(acc.x); acc.y = elu(acc.y); acc.z = elu(acc.z); acc.w = elu(acc.w);
        *reinterpret_cast<float4*>(hio + n * HF + lane * 4) = acc;
        __half2 h0 = __floats2half2_rn(acc.x, acc.y);
        __half2 h1 = __floats2half2_rn(acc.z, acc.w);
        uint2 u = make_uint2(*reinterpret_cast<unsigned*>(&h0),
                             *reinterpret_cast<unsigned*>(&h1));
        *reinterpret_cast<uint2*>(xh + n * HF + lane * 4) = u;
        float4 b4 = *reinterpret_cast<const float4*>(&b2[lane * 4]);
        *reinterpret_cast<float4*>(base2 + n * HF + lane * 4) =
            make_float4(acc.x + b4.x, acc.y + b4.y, acc.z + b4.z, acc.w + b4.w);
    } else {
        const int f0 = (lane & 7) * 4;
        float v = acc.x * Wp[f0] + acc.y * Wp[f0 + 1] + acc.z * Wp[f0 + 2] + acc.w * Wp[f0 + 3];
        #pragma unroll
        for (int off = 16; off; off >>= 1) v += __shfl_down_sync(0xffffffffu, v, off);
        if (lane == 0) out[n] = 0.25f * v + bp[0];
    }
}

// ---------------- launch ----------------
extern "C" void kernel_launch(void* const* d_in, const int* in_sizes, int n_in,
                              void* d_out, int out_size)
{
    const float* feats = (const float*)d_in[0];
    const int*   src   = (const int*)  d_in[1];
    const int*   dst   = (const int*)  d_in[2];
    const float* W1    = (const float*)d_in[3];
    const float* al1   = (const float*)d_in[4];
    const float* ar1   = (const float*)d_in[5];
    const float* b1    = (const float*)d_in[6];
    const float* W2    = (const float*)d_in[7];
    const float* al2   = (const float*)d_in[8];
    const float* ar2   = (const float*)d_in[9];
    const float* b2    = (const float*)d_in[10];
    const float* Wp    = (const float*)d_in[11];
    const float* bp    = (const float*)d_in[12];
    float* out = (float*)d_out;

    const int E = in_sizes[1];

    float *z, *acc1, *acc2, *el, *er;
    __half *xh, *w1h, *w2h;
    int *cnt, *bucket, *posarr;
    float4* evb;
    cudaGetSymbolAddress((void**)&z,      g_z);
    cudaGetSymbolAddress((void**)&acc1,   g_acc1);
    cudaGetSymbolAddress((void**)&acc2,   g_acc2);
    cudaGetSymbolAddress((void**)&el,     g_el);
    cudaGetSymbolAddress((void**)&er,     g_er);
    cudaGetSymbolAddress((void**)&xh,     g_xh);
    cudaGetSymbolAddress((void**)&w1h,    g_w1h);
    cudaGetSymbolAddress((void**)&w2h,    g_w2h);
    cudaGetSymbolAddress((void**)&cnt,    g_cnt);
    cudaGetSymbolAddress((void**)&bucket, g_bucket);
    cudaGetSymbolAddress((void**)&posarr, g_posarr);
    cudaGetSymbolAddress((void**)&evb,    g_evb);

    const int fill_grid = ((E + 3) / 4 + 255) / 256;
    const int conv_grid = (N_NODES * HF / 4 + 255) / 256;
    const int gemm_grid = (N_NODES + GBLK - 1) / GBLK;
    const int edge_grid = (E + 255) / 256;
    const int agg_grid  = (N_NODES + 7) / 8;

    // ---- adjacency build + fp16 conversions ----
    cudaMemsetAsync(cnt, 0, N_NODES * sizeof(int));
    fill_bucket_kernel<<<fill_grid, 256>>>(src, dst, E, cnt, bucket, posarr);
    conv_w_kernel<<<(HF * HF + 255) / 256, 256>>>(W1, W2, w1h, w2h);
    conv_x_kernel<<<conv_grid, 256>>>(feats, b1, xh, acc1);

    // ---- layer 1 ----
    gemm_attn_kernel<<<gemm_grid, 256>>>(xh, w1h, al1, ar1, z, el, er);
    attn_edge_kernel<<<edge_grid, 256>>>(src, dst, posarr, E, el, er, evb);
    gat_aggregate_kernel<0><<<agg_grid, 256>>>(cnt, bucket, (const float*)evb, z, acc1,
                                               xh, acc2, b2, Wp, bp, out);

    // ---- layer 2 (xh/acc2 prepared by aggregate<0>) ----
    gemm_attn_kernel<<<gemm_grid, 256>>>(xh, w2h, al2, ar2, z, el, er);
    attn_edge_kernel<<<edge_grid, 256>>>(src, dst, posarr, E, el, er, evb);
    gat_aggregate_kernel<1><<<agg_grid, 256>>>(cnt, bucket, (const float*)evb, z, acc2,
                                               xh, acc2, b2, Wp, bp, out);
}

// round 17
// speedup vs baseline: 1.1731x; 1.1731x over previous
#include <cuda_runtime.h>
#include <cuda_fp16.h>

#define N_NODES 50000
#define HF 128          // H*F
#define H_HEADS 4
#define DEG_CAP 128     // bucket capacity; deg ~ Poisson(16), P(>128) < 1e-60
#define GBLK 128        // nodes per GEMM block
#define KCH 32          // K chunk (2 k-steps of 16)
#define XS_STRIDE 40    // fp16 per row (80B: conflict-free ldmatrix, 16B-aligned)
#define WS_STRIDE 136   // fp16 per row (272B: conflict-free ldmatrix.trans)

// ---------------- scratch (static device globals; no allocation) ----------------
__device__ __half g_zh[N_NODES * HF];    // z in fp16 (gather path)
__device__ float  g_acc1[N_NODES * HF];  // layer-1 base -> elu(h1)
__device__ float  g_acc2[N_NODES * HF];  // layer-2 base (residual + bias)
__device__ float  g_el[N_NODES * H_HEADS];
__device__ float  g_er[N_NODES * H_HEADS];
__device__ __half g_xh[N_NODES * HF];    // fp16 GEMM input
__device__ __half g_w1h[HF * HF];
__device__ __half g_w2h[HF * HF];
__device__ int    g_cnt[N_NODES];
__device__ int    g_bucket[N_NODES * DEG_CAP];   // 25.6 MB

__device__ __forceinline__ float leaky(float v) { return v > 0.f ? v : 0.2f * v; }
__device__ __forceinline__ float elu(float v)   { return v > 0.f ? v : (__expf(v) - 1.f); }

__device__ __forceinline__ unsigned smem_u32(const void* p) {
    unsigned a;
    asm("{ .reg .u64 t; cvta.to.shared.u64 t, %1; cvt.u32.u64 %0, t; }" : "=r"(a) : "l"(p));
    return a;
}

// ---------------- bucket fill ----------------
__global__ void fill_bucket_kernel(const int* __restrict__ src, const int* __restrict__ dst,
                                   int E, int* __restrict__ cnt, int* __restrict__ bucket) {
    int i = blockIdx.x * blockDim.x + threadIdx.x;
    int e0 = i * 4;
    if (e0 + 4 <= E) {
        int4 d4 = *reinterpret_cast<const int4*>(dst + e0);
        int4 s4 = *reinterpret_cast<const int4*>(src + e0);
        int p0 = atomicAdd(&cnt[d4.x], 1);
        int p1 = atomicAdd(&cnt[d4.y], 1);
        int p2 = atomicAdd(&cnt[d4.z], 1);
        int p3 = atomicAdd(&cnt[d4.w], 1);
        bucket[d4.x * DEG_CAP + p0] = s4.x;
        bucket[d4.y * DEG_CAP + p1] = s4.y;
        bucket[d4.z * DEG_CAP + p2] = s4.z;
        bucket[d4.w * DEG_CAP + p3] = s4.w;
    } else {
        for (int e = e0; e < E; e++) {
            int dn = dst[e];
            int pos = atomicAdd(&cnt[dn], 1);
            bucket[dn * DEG_CAP + pos] = src[e];
        }
    }
}

// ---------------- converters ----------------
// feats -> fp16 xh ; base1 = feats + b1
__global__ void conv_x_kernel(const float* __restrict__ x, const float* __restrict__ bias,
                              __half* __restrict__ xh, float* __restrict__ base) {
    int idx = blockIdx.x * blockDim.x + threadIdx.x;       // float4 index
    if (idx >= N_NODES * HF / 4) return;
    float4 v = reinterpret_cast<const float4*>(x)[idx];
    int c = (idx * 4) & (HF - 1);
    float4 b = *reinterpret_cast<const float4*>(&bias[c]);
    reinterpret_cast<float4*>(base)[idx] =
        make_float4(v.x + b.x, v.y + b.y, v.z + b.z, v.w + b.w);
    __half2 h0 = __floats2half2_rn(v.x, v.y);
    __half2 h1 = __floats2half2_rn(v.z, v.w);
    uint2 u = make_uint2(*reinterpret_cast<unsigned*>(&h0), *reinterpret_cast<unsigned*>(&h1));
    reinterpret_cast<uint2*>(xh)[idx] = u;
}

__global__ void conv_w_kernel(const float* __restrict__ W1, const float* __restrict__ W2,
                              __half* __restrict__ W1h, __half* __restrict__ W2h) {
    int i = blockIdx.x * blockDim.x + threadIdx.x;
    if (i < HF * HF) {
        W1h[i] = __float2half_rn(W1[i]);
        W2h[i] = __float2half_rn(W2[i]);
    }
}

// ---------------- K1: tensor-core GEMM (mma.sync m16n8k16 f16->f32), fp16 z out --------
__global__ __launch_bounds__(256)
void gemm_attn_kernel(const __half* __restrict__ xh,
                      const __half* __restrict__ Wh,
                      const float* __restrict__ al,
                      const float* __restrict__ ar,
                      __half* __restrict__ zh,
                      float* __restrict__ el,
                      float* __restrict__ er)
{
    __shared__ __half xs[GBLK][XS_STRIDE];   // 10.2 KB
    __shared__ __half ws[KCH][WS_STRIDE];    //  8.7 KB

    const int tid  = threadIdx.x;
    const int w    = tid >> 5;
    const int lane = tid & 31;
    const int n0   = blockIdx.x * GBLK;

    float acc[16][4];
    #pragma unroll
    for (int nt = 0; nt < 16; nt++)
        #pragma unroll
        for (int c = 0; c < 4; c++) acc[nt][c] = 0.f;

    const int amat = lane >> 3;
    const int arow = (w << 4) + (lane & 7) + ((amat & 1) << 3);
    const int acol = (amat >> 1) << 3;
    const unsigned a_addr0 = smem_u32(&xs[arow][acol]);

    const int bl    = lane & 15;
    const int bkrow = (bl & 7) + ((bl >> 3) << 3);
    const unsigned b_addr0 = smem_u32(&ws[0][0]) + (unsigned)bkrow * (WS_STRIDE * 2);

    for (int kc = 0; kc < HF; kc += KCH) {
        #pragma unroll
        for (int it = 0; it < 2; it++) {
            int i   = tid + it * 256;
            int row = i >> 2, seg = i & 3;
            int n   = n0 + row;
            uint4 v = make_uint4(0u, 0u, 0u, 0u);
            if (n < N_NODES)
                v = *reinterpret_cast<const uint4*>(&xh[n * HF + kc + seg * 8]);
            *reinterpret_cast<uint4*>(&xs[row][seg * 8]) = v;
        }
        #pragma unroll
        for (int it = 0; it < 2; it++) {
            int i  = tid + it * 256;
            int k  = i >> 4, c8 = i & 15;
            uint4 v = *reinterpret_cast<const uint4*>(&Wh[(kc + k) * HF + c8 * 8]);
            *reinterpret_cast<uint4*>(&ws[k][c8 * 8]) = v;
        }
        __syncthreads();

        #pragma unroll
        for (int s = 0; s < 2; s++) {
            unsigned a0, a1, a2, a3;
            asm volatile("ldmatrix.sync.aligned.m8n8.x4.shared.b16 {%0,%1,%2,%3}, [%4];"
                         : "=r"(a0), "=r"(a1), "=r"(a2), "=r"(a3)
                         : "r"(a_addr0 + (unsigned)(s * 16 * 2)));
            unsigned b_base = b_addr0 + (unsigned)(s * 16 * (WS_STRIDE * 2));
            #pragma unroll
            for (int nt = 0; nt < 16; nt++) {
                unsigned b0, b1;
                asm volatile("ldmatrix.sync.aligned.m8n8.x2.trans.shared.b16 {%0,%1}, [%2];"
                             : "=r"(b0), "=r"(b1)
                             : "r"(b_base + (unsigned)(nt * 16)));
                asm volatile("mma.sync.aligned.m16n8k16.row.col.f32.f16.f16.f32 "
                             "{%0,%1,%2,%3},{%4,%5,%6,%7},{%8,%9},{%0,%1,%2,%3};"
                             : "+f"(acc[nt][0]), "+f"(acc[nt][1]),
                               "+f"(acc[nt][2]), "+f"(acc[nt][3])
                             : "r"(a0), "r"(a1), "r"(a2), "r"(a3), "r"(b0), "r"(b1));
            }
        }
        __syncthreads();
    }

    const int g = lane >> 2, t = lane & 3;
    const int nr0 = n0 + (w << 4) + g;
    const int nr1 = nr0 + 8;
    const bool v0 = (nr0 < N_NODES), v1 = (nr1 < N_NODES);

    float pl0[H_HEADS], pr0[H_HEADS], pl1[H_HEADS], pr1[H_HEADS];
    #pragma unroll
    for (int h = 0; h < H_HEADS; h++) { pl0[h] = pr0[h] = pl1[h] = pr1[h] = 0.f; }

    #pragma unroll
    for (int nt = 0; nt < 16; nt++) {
        int c = nt * 8 + t * 2;
        __half2 p0 = __floats2half2_rn(acc[nt][0], acc[nt][1]);
        __half2 p1 = __floats2half2_rn(acc[nt][2], acc[nt][3]);
        if (v0) *reinterpret_cast<__half2*>(&zh[nr0 * HF + c]) = p0;
        if (v1) *reinterpret_cast<__half2*>(&zh[nr1 * HF + c]) = p1;
        float2 alv = *reinterpret_cast<const float2*>(&al[c]);
        float2 arv = *reinterpret_cast<const float2*>(&ar[c]);
        int h = nt >> 2;
        pl0[h] += acc[nt][0] * alv.x + acc[nt][1] * alv.y;
        pr0[h] += acc[nt][0] * arv.x + acc[nt][1] * arv.y;
        pl1[h] += acc[nt][2] * alv.x + acc[nt][3] * alv.y;
        pr1[h] += acc[nt][2] * arv.x + acc[nt][3] * arv.y;
    }
    #pragma unroll
    for (int h = 0; h < H_HEADS; h++) {
        float a = pl0[h], b = pr0[h], cc = pl1[h], dd = pr1[h];
        a += __shfl_down_sync(0xffffffffu, a, 2);  a += __shfl_down_sync(0xffffffffu, a, 1);
        b += __shfl_down_sync(0xffffffffu, b, 2);  b += __shfl_down_sync(0xffffffffu, b, 1);
        cc += __shfl_down_sync(0xffffffffu, cc, 2); cc += __shfl_down_sync(0xffffffffu, cc, 1);
        dd += __shfl_down_sync(0xffffffffu, dd, 2); dd += __shfl_down_sync(0xffffffffu, dd, 1);
        if (t == 0) {
            if (v0) { el[nr0 * H_HEADS + h] = a;  er[nr0 * H_HEADS + h] = b;  }
            if (v1) { el[nr1 * H_HEADS + h] = cc; er[nr1 * H_HEADS + h] = dd; }
        }
    }
}

// ---------------- single-pass softmax-free aggregate, one warp per node, fp16 z --------
// MODE 0: elu(result) -> hio ; fp16 copy -> xh ; result+b2 -> base2
// MODE 1: head-mean + projection -> out[n]
template <int MODE>
__global__ __launch_bounds__(256)
void gat_aggregate_kernel(const int* __restrict__ cnt,
                          const int* __restrict__ bucket,
                          const float* __restrict__ el, const float* __restrict__ er,
                          const __half* __restrict__ zh,
                          float* __restrict__ hio,
                          __half* __restrict__ xh, float* __restrict__ base2,
                          const float* __restrict__ b2,
                          const float* __restrict__ Wp, const float* __restrict__ bp,
                          float* __restrict__ out)
{
    const int wid  = threadIdx.x >> 5;
    const int lane = threadIdx.x & 31;
    const int n    = blockIdx.x * 8 + wid;
    if (n >= N_NODES) return;

    const int beg = n * DEG_CAP;
    const int d   = cnt[n];
    const int h   = lane >> 3;

    const float erh = __ldg(&er[n * H_HEADS + h]);

    float  s   = 0.f;
    float4 acc = make_float4(0.f, 0.f, 0.f, 0.f);

    for (int i = 0; i < d; ++i) {
        int   sn = __ldg(&bucket[beg + i]);                        // warp-uniform
        float ev = __expf(leaky(__ldg(&el[sn * H_HEADS + h]) + erh));
        uint2 zr = *reinterpret_cast<const uint2*>(zh + sn * HF + lane * 4);
        float2 z01 = __half22float2(*reinterpret_cast<const __half2*>(&zr.x));
        float2 z23 = __half22float2(*reinterpret_cast<const __half2*>(&zr.y));
        s     += ev;
        acc.x += ev * z01.x;
        acc.y += ev * z01.y;
        acc.z += ev * z23.x;
        acc.w += ev * z23.y;
    }

    const float sinv = 1.f / fmaxf(s, 1e-9f);
    float4 base = *reinterpret_cast<const float4*>(hio + n * HF + lane * 4);
    acc.x = base.x + acc.x * sinv;
    acc.y = base.y + acc.y * sinv;
    acc.z = base.z + acc.z * sinv;
    acc.w = base.w + acc.w * sinv;

    if (MODE == 0) {
        acc.x = elu(acc.x); acc.y = elu(acc.y); acc.z = elu(acc.z); acc.w = elu(acc.w);
        *reinterpret_cast<float4*>(hio + n * HF + lane * 4) = acc;
        __half2 h0 = __floats2half2_rn(acc.x, acc.y);
        __half2 h1 = __floats2half2_rn(acc.z, acc.w);
        uint2 u = make_uint2(*reinterpret_cast<unsigned*>(&h0),
                             *reinterpret_cast<unsigned*>(&h1));
        *reinterpret_cast<uint2*>(xh + n * HF + lane * 4) = u;
        float4 b4 = *reinterpret_cast<const float4*>(&b2[lane * 4]);
        *reinterpret_cast<float4*>(base2 + n * HF + lane * 4) =
            make_float4(acc.x + b4.x, acc.y + b4.y, acc.z + b4.z, acc.w + b4.w);
    } else {
        const int f0 = (lane & 7) * 4;
        float v = acc.x * Wp[f0] + acc.y * Wp[f0 + 1] + acc.z * Wp[f0 + 2] + acc.w * Wp[f0 + 3];
        #pragma unroll
        for (int off = 16; off; off >>= 1) v += __shfl_down_sync(0xffffffffu, v, off);
        if (lane == 0) out[n] = 0.25f * v + bp[0];
    }
}

// ---------------- launch ----------------
extern "C" void kernel_launch(void* const* d_in, const int* in_sizes, int n_in,
                              void* d_out, int out_size)
{
    const float* feats = (const float*)d_in[0];
    const int*   src   = (const int*)  d_in[1];
    const int*   dst   = (const int*)  d_in[2];
    const float* W1    = (const float*)d_in[3];
    const float* al1   = (const float*)d_in[4];
    const float* ar1   = (const float*)d_in[5];
    const float* b1    = (const float*)d_in[6];
    const float* W2    = (const float*)d_in[7];
    const float* al2   = (const float*)d_in[8];
    const float* ar2   = (const float*)d_in[9];
    const float* b2    = (const float*)d_in[10];
    const float* Wp    = (const float*)d_in[11];
    const float* bp    = (const float*)d_in[12];
    float* out = (float*)d_out;

    const int E = in_sizes[1];

    float *acc1, *acc2, *el, *er;
    __half *zh, *xh, *w1h, *w2h;
    int *cnt, *bucket;
    cudaGetSymbolAddress((void**)&zh,     g_zh);
    cudaGetSymbolAddress((void**)&acc1,   g_acc1);
    cudaGetSymbolAddress((void**)&acc2,   g_acc2);
    cudaGetSymbolAddress((void**)&el,     g_el);
    cudaGetSymbolAddress((void**)&er,     g_er);
    cudaGetSymbolAddress((void**)&xh,     g_xh);
    cudaGetSymbolAddress((void**)&w1h,    g_w1h);
    cudaGetSymbolAddress((void**)&w2h,    g_w2h);
    cudaGetSymbolAddress((void**)&cnt,    g_cnt);
    cudaGetSymbolAddress((void**)&bucket, g_bucket);

    const int fill_grid = ((E + 3) / 4 + 255) / 256;
    const int conv_grid = (N_NODES * HF / 4 + 255) / 256;
    const int gemm_grid = (N_NODES + GBLK - 1) / GBLK;
    const int agg_grid  = (N_NODES + 7) / 8;

    // ---- adjacency build + fp16 conversions ----
    cudaMemsetAsync(cnt, 0, N_NODES * sizeof(int));
    fill_bucket_kernel<<<fill_grid, 256>>>(src, dst, E, cnt, bucket);
    conv_w_kernel<<<(HF * HF + 255) / 256, 256>>>(W1, W2, w1h, w2h);
    conv_x_kernel<<<conv_grid, 256>>>(feats, b1, xh, acc1);

    // ---- layer 1 ----
    gemm_attn_kernel<<<gemm_grid, 256>>>(xh, w1h, al1, ar1, zh, el, er);
    gat_aggregate_kernel<0><<<agg_grid, 256>>>(cnt, bucket, el, er, zh, acc1,
                                               xh, acc2, b2, Wp, bp, out);

    // ---- layer 2 (xh/acc2 prepared by aggregate<0>) ----
    gemm_attn_kernel<<<gemm_grid, 256>>>(xh, w2h, al2, ar2, zh, el, er);
    gat_aggregate_kernel<1><<<agg_grid, 256>>>(cnt, bucket, el, er, zh, acc2,
                                               xh, acc2, b2, Wp, bp, out);
}